// round 13
// baseline (speedup 1.0000x reference)
#include <cuda_runtime.h>

// out[j]     = dot(X[r1(j)], p), r1(j) = inds1[2j]*28 + inds1[2j+1], j in [0,100)
// out[100+j] = dot(Y[r2(j)], p)
// Persistent balanced schedule: 148 CTAs (one per SM, single wave) x 1024 thr.
// 400 half-row units (dot x 2 segs); CTA b owns units [b*400/148,(b+1)*400/148)
// -> 2 or 3 units each (11% imbalance vs 48% for 200-CTA grid). Per unit: 8
// front-batched LDG.128/thread, block reduce, spread per-dot counter combine.

#define Q      32768
#define QV     (Q / 4)       // 8192 float4 per row
#define NSEG   2
#define SEGF4  (QV / NSEG)   // 4096 float4 per half row
#define NT     1024
#define W_DIM  28
#define NDOTS  200
#define NUNIT  (NDOTS * NSEG)  // 400
#define NCTA   148

__device__ float        g_partial[NUNIT];
__device__ unsigned int g_cnt[NDOTS];   // zero-init; finisher resets each launch

__device__ __forceinline__ float dot4(float4 a, float4 b) {
    return a.x * b.x + a.y * b.y + a.z * b.z + a.w * b.w;
}

__global__ __launch_bounds__(NT, 1)
void persistent_dot_kernel(const float* __restrict__ X,
                           const float* __restrict__ Y,
                           const float* __restrict__ p,
                           const int*   __restrict__ inds1,
                           const int*   __restrict__ inds2,
                           float* __restrict__ out)
{
    const int b = blockIdx.x;                       // 0..147
    const int u_beg = (b * NUNIT) / NCTA;
    const int u_end = ((b + 1) * NUNIT) / NCTA;     // 2 or 3 units

    const float4* __restrict__ pv = reinterpret_cast<const float4*>(p);

    __shared__ float warp_sums[NT / 32];
    const int lane = threadIdx.x & 31;
    const int wid  = threadIdx.x >> 5;

    for (int u = u_beg; u < u_end; u++) {
        const int j   = u >> 1;                     // dot 0..199
        const int seg = u & 1;

        const bool second = (j >= 100);
        const int jj = second ? (j - 100) : j;
        const int* __restrict__ inds = second ? inds2 : inds1;
        const float* __restrict__ M  = second ? Y : X;

        const int i0 = seg * SEGF4 + threadIdx.x;

        // p loads first (independent of the inds->row chain)
        float4 p0 = pv[i0];
        float4 p1 = pv[i0 +     NT];
        float4 p2 = pv[i0 + 2 * NT];
        float4 p3 = pv[i0 + 3 * NT];

        const int r = inds[2 * jj] * W_DIM + inds[2 * jj + 1];
        const float4* __restrict__ row =
            reinterpret_cast<const float4*>(M + (size_t)r * Q);

        float4 a0 = row[i0];
        float4 a1 = row[i0 +     NT];
        float4 a2 = row[i0 + 2 * NT];
        float4 a3 = row[i0 + 3 * NT];

        float sum = dot4(a0, p0);
        sum += dot4(a1, p1);
        sum += dot4(a2, p2);
        sum += dot4(a3, p3);

        // warp reduce
        #pragma unroll
        for (int off = 16; off > 0; off >>= 1)
            sum += __shfl_xor_sync(0xFFFFFFFFu, sum, off);

        if (lane == 0) warp_sums[wid] = sum;
        __syncthreads();

        if (threadIdx.x == 0) {
            float s = warp_sums[0];
            #pragma unroll
            for (int w = 1; w < NT / 32; w++) s += warp_sums[w];

            g_partial[u] = s;
            __threadfence();                            // publish partial
            unsigned int t = atomicAdd(&g_cnt[j], 1u);  // spread counters
            if (t == NSEG - 1) {
                __threadfence();                        // acquire peer partial
                const volatile float* gp = g_partial + j * NSEG;
                out[j] = gp[0] + gp[1];                 // fixed order
                g_cnt[j] = 0;                           // reset for replay
            }
        }
        __syncthreads();    // protect warp_sums reuse across units
    }
}

extern "C" void kernel_launch(void* const* d_in, const int* in_sizes, int n_in,
                              void* d_out, int out_size)
{
    const float* X   = (const float*)d_in[0];
    const float* Y   = (const float*)d_in[1];
    const float* p   = (const float*)d_in[2];
    const int* inds1 = (const int*)d_in[3];
    const int* inds2 = (const int*)d_in[4];
    float* out       = (float*)d_out;

    persistent_dot_kernel<<<NCTA, NT>>>(X, Y, p, inds1, inds2, out);
}